// round 10
// baseline (speedup 1.0000x reference)
#include <cuda_runtime.h>
#include <cuda_fp16.h>
#include <cstdint>

#define KDIM  2304
#define NCH   512
#define MPOS  8192
#define IN_CH 256

// Scratch globals (no runtime allocation allowed)
__device__ __half g_wf[(size_t)NCH  * KDIM];   // [ch][k]
__device__ __half g_cf[(size_t)MPOS * KDIM];   // [n][k] == natural unfold (b,f,l)

union Pack8 { __half h[8]; uint4 u; };

// ---------------- helpers ----------------
static __device__ __forceinline__ uint32_t smem_u32(const void* p) {
    uint32_t a;
    asm("{ .reg .u64 t; cvta.to.shared.u64 t, %1; cvt.u32.u64 %0, t; }" : "=r"(a) : "l"(p));
    return a;
}
static __device__ __forceinline__ void cp_async16(uint32_t dst, const void* src) {
    asm volatile("cp.async.cg.shared.global [%0], [%1], 16;" :: "r"(dst), "l"(src));
}
#define CP_COMMIT() asm volatile("cp.async.commit_group;" ::: "memory")
#define CP_WAIT(N)  asm volatile("cp.async.wait_group %0;" :: "n"(N) : "memory")

static __device__ __forceinline__ void ldsm4(uint32_t* r, uint32_t a) {
    asm volatile("ldmatrix.sync.aligned.m8n8.x4.shared.b16 {%0,%1,%2,%3}, [%4];"
        : "=r"(r[0]), "=r"(r[1]), "=r"(r[2]), "=r"(r[3]) : "r"(a));
}
static __device__ __forceinline__ void mma16816(float* d, const uint32_t* a, const uint32_t* b) {
    asm volatile(
        "mma.sync.aligned.m16n8k16.row.col.f32.f16.f16.f32 "
        "{%0,%1,%2,%3}, {%4,%5,%6,%7}, {%8,%9}, {%0,%1,%2,%3};"
        : "+f"(d[0]), "+f"(d[1]), "+f"(d[2]), "+f"(d[3])
        : "r"(a[0]), "r"(a[1]), "r"(a[2]), "r"(a[3]), "r"(b[0]), "r"(b[1]));
}

// ---------------------------------------------------------------------------
// Fused prep kernel (unchanged from the 78us kernel).
//  Blocks [0, 288): wexpand (blk = p*36+q, w-row staged in smem).
//  Blocks [288, +8*2304): natural-order unfold; the [n][k] GEMM operand is
//  the same linear buffer (index identity (b*1024+m)*2304+k == b*2359296 + f*1024+l).
// ---------------------------------------------------------------------------
#define WBLOCKS 288
__global__ void prep_kernel(const float* __restrict__ x, const float* __restrict__ w) {
    const int blk = blockIdx.x;
    const int tid = threadIdx.x;

    if (blk < WBLOCKS) {
        __shared__ float wrow[64];
        const int p = blk / 36, q = blk - p * 36;
        if (tid < 64) wrow[tid] = w[blk * 64 + tid];
        __syncthreads();
        const int t  = tid >> 1;             // 0..63
        const int s0 = (tid & 1) * 32;       // 0 or 32
        const size_t base = (size_t)(p * 64 + t) * KDIM + q * 64 + s0;
        #pragma unroll
        for (int u = 0; u < 4; u++) {
            Pack8 pk;
            #pragma unroll
            for (int e = 0; e < 8; e++)
                pk.h[e] = __float2half(wrow[(t - (s0 + u * 8 + e)) & 63]);
            *(uint4*)(g_wf + base + u * 8) = pk.u;
        }
        return;
    }

    const int idx = blk - WBLOCKS;           // 0 .. 8*2304-1
    const int b = idx / KDIM;
    const int f = idx - b * KDIM;
    const int c = f / 9;
    const int r = f - c * 9;
    const int di = r / 3;
    const int dj = r - di * 3;

    const int l0  = tid * 8;                 // 128 threads x 8 elements
    const int i   = l0 >> 5;
    const int jj0 = l0 & 31;
    const int ii  = i + di - 1;
    const bool rowok = (unsigned)ii < 32u;
    const float* xr = x + ((size_t)(b * IN_CH + c) * 32 + ii) * 32;

    Pack8 pk;
    #pragma unroll
    for (int e = 0; e < 8; e++) {
        int jc = jj0 + e + dj - 1;
        float v = (rowok && (unsigned)jc < 32u) ? xr[jc] : 0.0f;
        pk.h[e] = __float2half(v);
    }
    *(uint4*)(g_cf + ((size_t)b * KDIM + f) * 1024 + l0) = pk.u;
}

// ---------------------------------------------------------------------------
// fp16 mma.sync GEMM.  C[ch][n] = sum_k W[ch][k] * Col[n][k]
// BM=128, BN=128, BK=64, 3-stage cp.async pipeline.
// 4 warps, warp tile 64x64.  Stall fixes vs prior round:
//  - single barrier per kt (trailing sync removed; top-of-next-iter sync
//    already orders readers before the overwriting prefetch, distance 3)
//  - prefetch issued inside the ks=0 LDSM latency shadow, not before it
//  - kt unrolled x3 to constant-fold stage indices
// ---------------------------------------------------------------------------
#define BK        64
#define NKITER    (KDIM / BK)        // 36
#define A_BYTES   (128 * 128)        // 16 KB
#define STAGE_BYTES (2 * A_BYTES)    // A + B = 32 KB
#define STAGES    3
#define SMEM_TOTAL (STAGES * STAGE_BYTES)   // 96 KB

__global__ __launch_bounds__(128, 2) void gemm_mma(float* __restrict__ out) {
    extern __shared__ char smem[];
    const int tid  = threadIdx.x;
    const int wid  = tid >> 5;
    const int lane = tid & 31;
    const int warp_m = wid >> 1;     // 0..1 -> 64-row slice of M
    const int warp_n = wid & 1;      // 0..1 -> 64-col slice of N

    const int m0 = blockIdx.y * 128;   // channel tile
    const int n0 = blockIdx.x * 128;   // row tile

    const uint32_t sbase = smem_u32(smem);

    const int crow = tid >> 3;               // 0..15 (plus i*16)
    const int cc   = tid & 7;                // 16B chunk within 128B row

    float acc[4][8][4];
    #pragma unroll
    for (int i = 0; i < 4; i++)
        #pragma unroll
        for (int jq = 0; jq < 8; jq++)
            #pragma unroll
            for (int e = 0; e < 4; e++) acc[i][jq][e] = 0.0f;

    auto issue = [&](int st, int k0) {
        uint32_t aDst = sbase + st * STAGE_BYTES;
        uint32_t bDst = aDst + A_BYTES;
        #pragma unroll
        for (int i = 0; i < 8; i++) {
            int row = crow + i * 16;          // 0..127
            uint32_t doff = row * 128 + ((cc ^ (row & 7)) * 16);
            cp_async16(aDst + doff, g_wf + (size_t)(m0 + row) * KDIM + k0 + cc * 8);
            cp_async16(bDst + doff, g_cf + (size_t)(n0 + row) * KDIM + k0 + cc * 8);
        }
    };

    // precomputed LDSM lane addressing (stage-relative)
    uint32_t aoff[4], boff[4];
    #pragma unroll
    for (int mt = 0; mt < 4; mt++) {
        int row = warp_m * 64 + mt * 16 + (lane & 15);
        aoff[mt] = row * 128 + ((lane >> 4) ^ (row & 7)) * 16;   // + ks*2 xor handled below
    }
    #pragma unroll
    for (int ntp = 0; ntp < 4; ntp++) {
        int row = warp_n * 64 + ntp * 16 + ((lane >> 4) << 3) + (lane & 7);
        boff[ntp] = row * 128 + (((lane >> 3) & 1) ^ (row & 7)) * 16;
    }

    issue(0, 0);  CP_COMMIT();
    issue(1, BK); CP_COMMIT();

    #pragma unroll 3
    for (int kt = 0; kt < NKITER; kt++) {
        CP_WAIT(1);
        __syncthreads();

        const uint32_t aBase = sbase + (kt % STAGES) * STAGE_BYTES;
        const uint32_t bBase = aBase + A_BYTES;

        // ---- ks = 0: fragment loads first, prefetch in their latency shadow
        uint32_t afr[4][4], bfr[4][4];
        #pragma unroll
        for (int mt = 0; mt < 4; mt++) {
            int row = warp_m * 64 + mt * 16 + (lane & 15);
            ldsm4(afr[mt], aBase + row * 128 + (((lane >> 4)) ^ (row & 7)) * 16);
        }
        #pragma unroll
        for (int ntp = 0; ntp < 4; ntp++) {
            int row = warp_n * 64 + ntp * 16 + ((lane >> 4) << 3) + (lane & 7);
            ldsm4(bfr[ntp], bBase + row * 128 + ((((lane >> 3) & 1)) ^ (row & 7)) * 16);
        }

        if (kt + 2 < NKITER) issue((kt + 2) % STAGES, (kt + 2) * BK);
        CP_COMMIT();

        #pragma unroll
        for (int mt = 0; mt < 4; mt++)
            #pragma unroll
            for (int nt = 0; nt < 8; nt++)
                mma16816(acc[mt][nt], afr[mt], &bfr[nt >> 1][(nt & 1) * 2]);

        // ---- ks = 1..3
        #pragma unroll
        for (int ks = 1; ks < 4; ks++) {
            #pragma unroll
            for (int mt = 0; mt < 4; mt++) {
                int row = warp_m * 64 + mt * 16 + (lane & 15);
                int ch  = (2 * ks + (lane >> 4)) ^ (row & 7);
                ldsm4(afr[mt], aBase + row * 128 + ch * 16);
            }
            #pragma unroll
            for (int ntp = 0; ntp < 4; ntp++) {
                int row = warp_n * 64 + ntp * 16 + ((lane >> 4) << 3) + (lane & 7);
                int ch  = (2 * ks + ((lane >> 3) & 1)) ^ (row & 7);
                ldsm4(bfr[ntp], bBase + row * 128 + ch * 16);
            }
            #pragma unroll
            for (int mt = 0; mt < 4; mt++)
                #pragma unroll
                for (int nt = 0; nt < 8; nt++)
                    mma16816(acc[mt][nt], afr[mt], &bfr[nt >> 1][(nt & 1) * 2]);
        }
        // no trailing __syncthreads(): the next iteration's top barrier
        // orders all readers of this stage before its overwrite (distance 3)
    }

    // Epilogue: out[b, ch, pos];  n-tile (128 rows) stays within one batch.
    const int b    = n0 >> 10;
    const int pos0 = (n0 & 1023) + warp_n * 64 + (lane & 3) * 2;
    const int chb  = m0 + warp_m * 64 + (lane >> 2);
    #pragma unroll
    for (int mt = 0; mt < 4; mt++) {
        #pragma unroll
        for (int nt = 0; nt < 8; nt++) {
            float* o0 = out + ((size_t)b * NCH + chb + mt * 16) * 1024 + pos0 + nt * 8;
            *(float2*)o0              = make_float2(acc[mt][nt][0], acc[mt][nt][1]);
            *(float2*)(o0 + 8 * 1024) = make_float2(acc[mt][nt][2], acc[mt][nt][3]);
        }
    }
}

// ---------------------------------------------------------------------------
extern "C" void kernel_launch(void* const* d_in, const int* in_sizes, int n_in,
                              void* d_out, int out_size) {
    const float* x = (const float*)d_in[0];   // [8, 256, 32, 32]
    const float* w = (const float*)d_in[1];   // [8, 36, 64]
    float* out = (float*)d_out;               // [8, 512, 32, 32]

    cudaFuncSetAttribute(gemm_mma, cudaFuncAttributeMaxDynamicSharedMemorySize, SMEM_TOTAL);

    prep_kernel<<<WBLOCKS + 8 * KDIM, 128>>>(x, w);
    gemm_mma<<<dim3(MPOS / 128, NCH / 128), 128, SMEM_TOTAL>>>(out);
}

// round 12
// speedup vs baseline: 1.3910x; 1.3910x over previous
#include <cuda_runtime.h>
#include <cuda_fp16.h>
#include <cstdint>

#define KDIM  2304
#define NCH   512
#define MPOS  8192
#define IN_CH 256

// Scratch globals (no runtime allocation allowed)
__device__ __half g_wf[(size_t)NCH  * KDIM];   // [ch][k]
__device__ __half g_cf[(size_t)MPOS * KDIM];   // [n][k] == natural unfold (b,f,l)

union Pack8 { __half h[8]; uint4 u; };

// ---------------- helpers ----------------
static __device__ __forceinline__ uint32_t smem_u32(const void* p) {
    uint32_t a;
    asm("{ .reg .u64 t; cvta.to.shared.u64 t, %1; cvt.u32.u64 %0, t; }" : "=r"(a) : "l"(p));
    return a;
}
static __device__ __forceinline__ void cp_async16(uint32_t dst, const void* src) {
    asm volatile("cp.async.cg.shared.global [%0], [%1], 16;" :: "r"(dst), "l"(src));
}
#define CP_COMMIT() asm volatile("cp.async.commit_group;" ::: "memory")
#define CP_WAIT(N)  asm volatile("cp.async.wait_group %0;" :: "n"(N) : "memory")

static __device__ __forceinline__ void ldsm4(uint32_t* r, uint32_t a) {
    asm volatile("ldmatrix.sync.aligned.m8n8.x4.shared.b16 {%0,%1,%2,%3}, [%4];"
        : "=r"(r[0]), "=r"(r[1]), "=r"(r[2]), "=r"(r[3]) : "r"(a));
}
static __device__ __forceinline__ void mma16816(float* d, const uint32_t* a, const uint32_t* b) {
    asm volatile(
        "mma.sync.aligned.m16n8k16.row.col.f32.f16.f16.f32 "
        "{%0,%1,%2,%3}, {%4,%5,%6,%7}, {%8,%9}, {%0,%1,%2,%3};"
        : "+f"(d[0]), "+f"(d[1]), "+f"(d[2]), "+f"(d[3])
        : "r"(a[0]), "r"(a[1]), "r"(a[2]), "r"(a[3]), "r"(b[0]), "r"(b[1]));
}

// ---------------------------------------------------------------------------
// Fused prep kernel (unchanged from the 78us kernel).
//  Blocks [0, 288): wexpand (blk = p*36+q, w-row staged in smem).
//  Blocks [288, +8*2304): natural-order unfold; the [n][k] GEMM operand is
//  the same linear buffer (index identity (b*1024+m)*2304+k == b*2359296 + f*1024+l).
// ---------------------------------------------------------------------------
#define WBLOCKS 288
__global__ void prep_kernel(const float* __restrict__ x, const float* __restrict__ w) {
    const int blk = blockIdx.x;
    const int tid = threadIdx.x;

    if (blk < WBLOCKS) {
        __shared__ float wrow[64];
        const int p = blk / 36, q = blk - p * 36;
        if (tid < 64) wrow[tid] = w[blk * 64 + tid];
        __syncthreads();
        const int t  = tid >> 1;             // 0..63
        const int s0 = (tid & 1) * 32;       // 0 or 32
        const size_t base = (size_t)(p * 64 + t) * KDIM + q * 64 + s0;
        #pragma unroll
        for (int u = 0; u < 4; u++) {
            Pack8 pk;
            #pragma unroll
            for (int e = 0; e < 8; e++)
                pk.h[e] = __float2half(wrow[(t - (s0 + u * 8 + e)) & 63]);
            *(uint4*)(g_wf + base + u * 8) = pk.u;
        }
        return;
    }

    const int idx = blk - WBLOCKS;           // 0 .. 8*2304-1
    const int b = idx / KDIM;
    const int f = idx - b * KDIM;
    const int c = f / 9;
    const int r = f - c * 9;
    const int di = r / 3;
    const int dj = r - di * 3;

    const int l0  = tid * 8;                 // 128 threads x 8 elements
    const int i   = l0 >> 5;
    const int jj0 = l0 & 31;
    const int ii  = i + di - 1;
    const bool rowok = (unsigned)ii < 32u;
    const float* xr = x + ((size_t)(b * IN_CH + c) * 32 + ii) * 32;

    Pack8 pk;
    #pragma unroll
    for (int e = 0; e < 8; e++) {
        int jc = jj0 + e + dj - 1;
        float v = (rowok && (unsigned)jc < 32u) ? xr[jc] : 0.0f;
        pk.h[e] = __float2half(v);
    }
    *(uint4*)(g_cf + ((size_t)b * KDIM + f) * 1024 + l0) = pk.u;
}

// ---------------------------------------------------------------------------
// fp16 mma.sync GEMM.  C[ch][n] = sum_k W[ch][k] * Col[n][k]
// BM=128, BN=128, BK=64, 3-stage cp.async pipeline, 8 warps (64x32 each).
// Exact R8 structure with exactly ONE change: the trailing per-iteration
// __syncthreads() is removed.  Safety: readers of stage kt%3 complete before
// the top barrier of iteration kt+1; the overwrite of that stage (issue at
// kt+1 targeting (kt+3)%3 = kt%3) happens after that same barrier.
// ---------------------------------------------------------------------------
#define BK        64
#define NKITER    (KDIM / BK)        // 36
#define A_BYTES   (128 * 128)        // 16 KB
#define STAGE_BYTES (2 * A_BYTES)    // A + B = 32 KB
#define STAGES    3
#define SMEM_TOTAL (STAGES * STAGE_BYTES)   // 96 KB

__global__ __launch_bounds__(256, 2) void gemm_mma(float* __restrict__ out) {
    extern __shared__ char smem[];
    const int tid  = threadIdx.x;
    const int wid  = tid >> 5;
    const int lane = tid & 31;
    const int warp_m = wid & 1;      // 0..1 -> 64-row slice of M
    const int warp_n = wid >> 1;     // 0..3 -> 32-col slice of N

    const int m0 = blockIdx.y * 128;   // channel tile
    const int n0 = blockIdx.x * 128;   // row tile

    const uint32_t sbase = smem_u32(smem);

    const int crow = tid >> 3;               // 0..31 (plus i*32)
    const int cc   = tid & 7;                // 16B chunk within 128B row

    float acc[4][4][4];
    #pragma unroll
    for (int i = 0; i < 4; i++)
        #pragma unroll
        for (int jq = 0; jq < 4; jq++)
            #pragma unroll
            for (int e = 0; e < 4; e++) acc[i][jq][e] = 0.0f;

    auto issue = [&](int st, int k0) {
        uint32_t aDst = sbase + st * STAGE_BYTES;
        uint32_t bDst = aDst + A_BYTES;
        #pragma unroll
        for (int i = 0; i < 4; i++) {
            int row = crow + i * 32;          // 0..127
            uint32_t doff = row * 128 + ((cc ^ (row & 7)) * 16);
            cp_async16(aDst + doff, g_wf + (size_t)(m0 + row) * KDIM + k0 + cc * 8);
            cp_async16(bDst + doff, g_cf + (size_t)(n0 + row) * KDIM + k0 + cc * 8);
        }
    };

    issue(0, 0);  CP_COMMIT();
    issue(1, BK); CP_COMMIT();

    for (int kt = 0; kt < NKITER; kt++) {
        CP_WAIT(1);
        __syncthreads();

        if (kt + 2 < NKITER) issue((kt + 2) % STAGES, (kt + 2) * BK);
        CP_COMMIT();

        const uint32_t aBase = sbase + (kt % STAGES) * STAGE_BYTES;
        const uint32_t bBase = aBase + A_BYTES;

        #pragma unroll
        for (int ks = 0; ks < 4; ks++) {       // k16 steps within BK=64
            uint32_t afr[4][4];
            #pragma unroll
            for (int mt = 0; mt < 4; mt++) {
                int row = warp_m * 64 + mt * 16 + (lane & 15);
                int ch  = (2 * ks + (lane >> 4)) ^ (row & 7);
                ldsm4(afr[mt], aBase + row * 128 + ch * 16);
            }
            uint32_t bfr[2][4];
            #pragma unroll
            for (int ntp = 0; ntp < 2; ntp++) {
                int row = warp_n * 32 + ntp * 16 + ((lane >> 4) << 3) + (lane & 7);
                int ch  = (2 * ks + ((lane >> 3) & 1)) ^ (row & 7);
                ldsm4(bfr[ntp], bBase + row * 128 + ch * 16);
            }
            #pragma unroll
            for (int mt = 0; mt < 4; mt++)
                #pragma unroll
                for (int nt = 0; nt < 4; nt++)
                    mma16816(acc[mt][nt], afr[mt], &bfr[nt >> 1][(nt & 1) * 2]);
        }
        // (single barrier per iteration -- trailing sync removed)
    }

    // Epilogue: out[b, ch, pos];  n-tile (128 rows) stays within one batch.
    const int b    = n0 >> 10;
    const int pos0 = (n0 & 1023) + warp_n * 32 + (lane & 3) * 2;
    const int chb  = m0 + warp_m * 64 + (lane >> 2);
    #pragma unroll
    for (int mt = 0; mt < 4; mt++) {
        #pragma unroll
        for (int nt = 0; nt < 4; nt++) {
            float* o0 = out + ((size_t)b * NCH + chb + mt * 16) * 1024 + pos0 + nt * 8;
            *(float2*)o0              = make_float2(acc[mt][nt][0], acc[mt][nt][1]);
            *(float2*)(o0 + 8 * 1024) = make_float2(acc[mt][nt][2], acc[mt][nt][3]);
        }
    }
}

// ---------------------------------------------------------------------------
extern "C" void kernel_launch(void* const* d_in, const int* in_sizes, int n_in,
                              void* d_out, int out_size) {
    const float* x = (const float*)d_in[0];   // [8, 256, 32, 32]
    const float* w = (const float*)d_in[1];   // [8, 36, 64]
    float* out = (float*)d_out;               // [8, 512, 32, 32]

    cudaFuncSetAttribute(gemm_mma, cudaFuncAttributeMaxDynamicSharedMemorySize, SMEM_TOTAL);

    prep_kernel<<<WBLOCKS + 8 * KDIM, 128>>>(x, w);
    gemm_mma<<<dim3(MPOS / 128, NCH / 128), 256, SMEM_TOTAL>>>(out);
}

// round 16
// speedup vs baseline: 1.6667x; 1.1981x over previous
#include <cuda_runtime.h>
#include <cuda_fp16.h>
#include <cstdint>

#define KDIM  2304
#define NCH   512
#define MPOS  8192
#define IN_CH 256

// Scratch globals (no runtime allocation allowed)
__device__ __half s_colbuf[(size_t)MPOS * KDIM];   // [n][k] == natural unfold (b,f,l)
__device__ __half s_wbuf[(size_t)NCH  * KDIM];     // [ch][k]

union Pk8 { __half h[8]; uint4 u; };

// ---------------- helpers ----------------
static __device__ __forceinline__ uint32_t sm_addr(const void* p) {
    uint32_t a;
    asm("{ .reg .u64 t; cvta.to.shared.u64 t, %1; cvt.u32.u64 %0, t; }" : "=r"(a) : "l"(p));
    return a;
}
static __device__ __forceinline__ void cpa16(uint32_t dst, const void* src) {
    asm volatile("cp.async.cg.shared.global [%0], [%1], 16;" :: "r"(dst), "l"(src));
}
#define CPA_COMMIT() asm volatile("cp.async.commit_group;" ::: "memory")
#define CPA_WAIT(N)  asm volatile("cp.async.wait_group %0;" :: "n"(N) : "memory")

static __device__ __forceinline__ void ldmx4(uint32_t* r, uint32_t a) {
    asm volatile("ldmatrix.sync.aligned.m8n8.x4.shared.b16 {%0,%1,%2,%3}, [%4];"
        : "=r"(r[0]), "=r"(r[1]), "=r"(r[2]), "=r"(r[3]) : "r"(a));
}
static __device__ __forceinline__ void hmma(float* d, const uint32_t* a, const uint32_t* b) {
    asm volatile(
        "mma.sync.aligned.m16n8k16.row.col.f32.f16.f16.f32 "
        "{%0,%1,%2,%3}, {%4,%5,%6,%7}, {%8,%9}, {%0,%1,%2,%3};"
        : "+f"(d[0]), "+f"(d[1]), "+f"(d[2]), "+f"(d[3])
        : "r"(a[0]), "r"(a[1]), "r"(a[2]), "r"(a[3]), "r"(b[0]), "r"(b[1]));
}

// ---------------------------------------------------------------------------
// Fused prep kernel.
//  Blocks [0, 288): wexpand (blk = p*36+q, w-row staged in smem).
//  Blocks [288, +2048): im2col. blk-288 = b*256 + c.  Stage x[b][c]
//  (32x32 floats) in padded smem ONCE, then emit all 9 (di,dj) shifted
//  fp16 variants -> 9x fewer gmem reads than a per-f gather.
//  Output layout = natural unfold (b,f,l), which IS the [n][k] GEMM operand
//  (index identity (b*1024+m)*2304+k == b*2359296 + f*1024 + l).
// ---------------------------------------------------------------------------
#define WBLOCKS 288
__global__ void stage_inputs(const float* __restrict__ x, const float* __restrict__ w) {
    const int blk = blockIdx.x;
    const int tid = threadIdx.x;

    if (blk < WBLOCKS) {
        __shared__ float wrow[64];
        const int p = blk / 36, q = blk - p * 36;
        if (tid < 64) wrow[tid] = w[blk * 64 + tid];
        __syncthreads();
        const int t  = tid >> 1;             // 0..63
        const int s0 = (tid & 1) * 32;       // 0 or 32
        const size_t base = (size_t)(p * 64 + t) * KDIM + q * 64 + s0;
        #pragma unroll
        for (int u = 0; u < 4; u++) {
            Pk8 pk;
            #pragma unroll
            for (int e = 0; e < 8; e++)
                pk.h[e] = __float2half(wrow[(t - (s0 + u * 8 + e)) & 63]);
            *(uint4*)(s_wbuf + base + u * 8) = pk.u;
        }
        return;
    }

    // im2col: one block per (b, c)
    const int idx = blk - WBLOCKS;           // 0..2047
    const int b = idx >> 8;
    const int c = idx & 255;

    __shared__ float xs[32 * 33];            // padded rows: conflict-free shifts
    {
        const float* xp = x + ((size_t)(b * IN_CH + c) << 10);
        for (int i = tid; i < 1024; i += 128)
            xs[(i >> 5) * 33 + (i & 31)] = xp[i];
    }
    __syncthreads();

    const int l0 = tid * 8;                  // 128 threads x 8 elements
    const int i0 = l0 >> 5;
    const int j0 = l0 & 31;
    size_t obase = ((size_t)b * KDIM + c * 9) * 1024 + l0;

    #pragma unroll
    for (int di = 0; di < 3; di++) {
        const int ii = i0 + di - 1;
        const bool rowok = (unsigned)ii < 32u;
        const float* xrow = xs + ii * 33;
        #pragma unroll
        for (int dj = 0; dj < 3; dj++) {
            Pk8 pk;
            #pragma unroll
            for (int e = 0; e < 8; e++) {
                int jc = j0 + e + dj - 1;
                float v = (rowok && (unsigned)jc < 32u) ? xrow[jc] : 0.0f;
                pk.h[e] = __float2half(v);
            }
            *(uint4*)(s_colbuf + obase + (size_t)(di * 3 + dj) * 1024) = pk.u;
        }
    }
}

// ---------------------------------------------------------------------------
// fp16 mma.sync GEMM.  C[ch][n] = sum_k W[ch][k] * Col[n][k]
// BM=128, BN=128, BK=64, 3-stage cp.async pipeline, 8 warps (64x32 each),
// single barrier per kt.  Per-warp ks rotation: warp wid walks the four
// k16 steps in order (wid, wid+1, wid+2, wid+3)&3, desynchronizing the
// LDSM and MMA phases across warps so the smem crossbar overlaps the
// tensor pipe instead of convoying with it.  Zero extra registers.
// ---------------------------------------------------------------------------
#define BK        64
#define NKITER    (KDIM / BK)        // 36
#define A_BYTES   (128 * 128)        // 16 KB
#define STAGE_BYTES (2 * A_BYTES)    // A + B = 32 KB
#define STAGES    3
#define SMEM_TOTAL (STAGES * STAGE_BYTES)   // 96 KB

__global__ __launch_bounds__(256, 2) void block_gemm(float* __restrict__ out) {
    extern __shared__ char smem[];
    const int tid  = threadIdx.x;
    const int wid  = tid >> 5;
    const int lane = tid & 31;
    const int warp_m = wid & 1;      // 0..1 -> 64-row slice of M
    const int warp_n = wid >> 1;     // 0..3 -> 32-col slice of N

    const int m0 = blockIdx.y * 128;   // channel tile
    const int n0 = blockIdx.x * 128;   // row tile

    const uint32_t sbase = sm_addr(smem);

    const int crow = tid >> 3;               // 0..31 (plus i*32)
    const int cc   = tid & 7;                // 16B chunk within 128B row

    float acc[4][4][4];
    #pragma unroll
    for (int i = 0; i < 4; i++)
        #pragma unroll
        for (int jq = 0; jq < 4; jq++)
            #pragma unroll
            for (int e = 0; e < 4; e++) acc[i][jq][e] = 0.0f;

    auto issue = [&](int st, int k0) {
        uint32_t aDst = sbase + st * STAGE_BYTES;
        uint32_t bDst = aDst + A_BYTES;
        #pragma unroll
        for (int i = 0; i < 4; i++) {
            int row = crow + i * 32;          // 0..127
            uint32_t doff = row * 128 + ((cc ^ (row & 7)) * 16);
            cpa16(aDst + doff, s_wbuf   + (size_t)(m0 + row) * KDIM + k0 + cc * 8);
            cpa16(bDst + doff, s_colbuf + (size_t)(n0 + row) * KDIM + k0 + cc * 8);
        }
    };

    issue(0, 0);  CPA_COMMIT();
    issue(1, BK); CPA_COMMIT();

    for (int kt = 0; kt < NKITER; kt++) {
        CPA_WAIT(1);
        __syncthreads();

        if (kt + 2 < NKITER) issue((kt + 2) % STAGES, (kt + 2) * BK);
        CPA_COMMIT();

        const uint32_t aBase = sbase + (kt % STAGES) * STAGE_BYTES;
        const uint32_t bBase = aBase + A_BYTES;

        #pragma unroll
        for (int ksi = 0; ksi < 4; ksi++) {    // per-warp rotated k16 order
            const int ks = (ksi + wid) & 3;
            uint32_t afr[4][4];
            #pragma unroll
            for (int mt = 0; mt < 4; mt++) {
                int row = warp_m * 64 + mt * 16 + (lane & 15);
                int ch  = (2 * ks + (lane >> 4)) ^ (row & 7);
                ldmx4(afr[mt], aBase + row * 128 + ch * 16);
            }
            uint32_t bfr[2][4];
            #pragma unroll
            for (int ntp = 0; ntp < 2; ntp++) {
                int row = warp_n * 32 + ntp * 16 + ((lane >> 4) << 3) + (lane & 7);
                int ch  = (2 * ks + ((lane >> 3) & 1)) ^ (row & 7);
                ldmx4(bfr[ntp], bBase + row * 128 + ch * 16);
            }
            #pragma unroll
            for (int mt = 0; mt < 4; mt++)
                #pragma unroll
                for (int nt = 0; nt < 4; nt++)
                    hmma(acc[mt][nt], afr[mt], &bfr[nt >> 1][(nt & 1) * 2]);
        }
        // single barrier per iteration (top of next kt orders stage reuse)
    }

    // Epilogue: out[b, ch, pos];  n-tile (128 rows) stays within one batch.
    const int b    = n0 >> 10;
    const int pos0 = (n0 & 1023) + warp_n * 32 + (lane & 3) * 2;
    const int chb  = m0 + warp_m * 64 + (lane >> 2);
    #pragma unroll
    for (int mt = 0; mt < 4; mt++) {
        #pragma unroll
        for (int nt = 0; nt < 4; nt++) {
            float* o0 = out + ((size_t)b * NCH + chb + mt * 16) * 1024 + pos0 + nt * 8;
            *(float2*)o0              = make_float2(acc[mt][nt][0], acc[mt][nt][1]);
            *(float2*)(o0 + 8 * 1024) = make_float2(acc[mt][nt][2], acc[mt][nt][3]);
        }
    }
}

// ---------------------------------------------------------------------------
extern "C" void kernel_launch(void* const* d_in, const int* in_sizes, int n_in,
                              void* d_out, int out_size) {
    const float* x = (const float*)d_in[0];   // [8, 256, 32, 32]
    const float* w = (const float*)d_in[1];   // [8, 36, 64]
    float* out = (float*)d_out;               // [8, 512, 32, 32]

    cudaFuncSetAttribute(block_gemm, cudaFuncAttributeMaxDynamicSharedMemorySize, SMEM_TOTAL);

    stage_inputs<<<WBLOCKS + 2048, 128>>>(x, w);
    block_gemm<<<dim3(MPOS / 128, NCH / 128), 256, SMEM_TOTAL>>>(out);
}